// round 6
// baseline (speedup 1.0000x reference)
#include <cuda_runtime.h>
#include <cstdint>

// Problem constants
#define NB 8
#define NC 64
#define NC3 192
#define NH 128
#define NW 128
#define HW (NH*NW)          // 16384

// ---------------- scratch (no cudaMalloc allowed) ----------------
__device__ float g_Y[(size_t)NB * NC3 * HW];   // concat buffer [b,192,h,w]  (~100.7 MB)
__device__ float g_W1f[64 * 64];
__device__ float g_W2f[64 * 64];
__device__ float g_b1f[64];
__device__ float g_b2f[64];
__device__ float g_alpha[192];
__device__ float g_betap[192];
__device__ float g_zero64[64];                 // zero-initialized

// =================================================================
// Kernel 0: fuse weights (W1f = Wx1@Wx, etc) and BN epilogue params
// =================================================================
__global__ void prep_kernel(const float* __restrict__ Wx,  const float* __restrict__ bx,
                            const float* __restrict__ Wx1, const float* __restrict__ bx1,
                            const float* __restrict__ Wx2, const float* __restrict__ bx2,
                            const float* __restrict__ b_msa,
                            const float* __restrict__ gamma, const float* __restrict__ beta,
                            const float* __restrict__ mean,  const float* __restrict__ var)
{
    int tid = threadIdx.x;
    for (int idx = tid; idx < 4096; idx += 256) {
        int o = idx >> 6, c = idx & 63;
        float s1 = 0.f, s2 = 0.f;
        for (int k = 0; k < 64; k++) {
            float wc = Wx[k * 64 + c];
            s1 = fmaf(Wx1[o * 64 + k], wc, s1);
            s2 = fmaf(Wx2[o * 64 + k], wc, s2);
        }
        g_W1f[idx] = s1;
        g_W2f[idx] = s2;
    }
    for (int o = tid; o < 64; o += 256) {
        float s1 = bx1[o], s2 = bx2[o];
        for (int k = 0; k < 64; k++) {
            float bk = bx[k];
            s1 = fmaf(Wx1[o * 64 + k], bk, s1);
            s2 = fmaf(Wx2[o * 64 + k], bk, s2);
        }
        g_b1f[o] = s1;
        g_b2f[o] = s2;
    }
    for (int o = tid; o < 192; o += 256) {
        float a = gamma[o] * rsqrtf(var[o] + 1e-4f);
        g_alpha[o] = a;
        g_betap[o] = fmaf(b_msa[o] - mean[o], a, beta[o]);
    }
}

// =================================================================
// Kernel 1: per-(b,h) attention stage, all GEMMs in shared memory
// =================================================================
#define LDM 132   // stride of 64x128 matrices (float4-aligned, bank-staggered)
#define LDT 68    // stride of transposed [k][o] matrices

#define OFF_A  0
#define OFF_P  (64 * LDM)
#define OFF_B1 (2 * 64 * LDM)
#define OFF_B2 (3 * 64 * LDM)
#define OFF_FT (4 * 64 * LDM)                  // 128 x LDT
#define OFF_ST (OFF_FT + 128 * LDT)            // 64 x LDT
#define OFF_WT (OFF_ST + 64 * LDT)             // 64 x LDT
#define ATTN_SMEM_FLOATS (OFF_WT + 64 * LDT)   // 51200 floats = 204800 B

// Load a 64x64 weight matrix G[o][k] (row-major) transposed into sWt[k*LDT+o]
__device__ __forceinline__ void load_wt(float* sWt, const float* __restrict__ G, int tid)
{
    for (int idx = tid; idx < 4096; idx += 256) {
        int o = idx >> 6, k = idx & 63;
        sWt[k * LDT + o] = G[idx];          // coalesced gmem read
    }
}

// Load a 64x128 pixel-row tile X[b, :, h, :] into sA (stride LDM)
__device__ __forceinline__ void load_tile(float* sA, const float* __restrict__ X,
                                          int b, int h, int tid)
{
    const float* src = X + (size_t)b * 64 * HW + h * NW;
    for (int idx = tid; idx < 8192; idx += 256) {
        int c = idx >> 7, w = idx & 127;
        sA[c * LDM + w] = src[c * HW + w];
    }
}

// C[o][w] = sum_k Wt[k][o] * A[k][w] + bias[o]   (64x128, K=64)
// TO_GMEM: write to global with row stride HW; else smem stride LDM.
template <bool TO_GMEM>
__device__ __forceinline__ void gemm_ow(const float* __restrict__ sWt,
                                        const float* __restrict__ sA,
                                        float* __restrict__ outp,
                                        const float* __restrict__ bias, int tid)
{
    int oc0 = (tid >> 4) << 2;
    int w0  = (tid & 15) << 3;
    float acc[4][8];
#pragma unroll
    for (int i = 0; i < 4; i++) {
        float bb = bias[oc0 + i];
#pragma unroll
        for (int j = 0; j < 8; j++) acc[i][j] = bb;
    }
#pragma unroll 4
    for (int k = 0; k < 64; k++) {
        float4 a0 = *(const float4*)(sA + k * LDM + w0);
        float4 a1 = *(const float4*)(sA + k * LDM + w0 + 4);
        float av[8] = {a0.x, a0.y, a0.z, a0.w, a1.x, a1.y, a1.z, a1.w};
#pragma unroll
        for (int i = 0; i < 4; i++) {
            float wv = sWt[k * LDT + oc0 + i];
#pragma unroll
            for (int j = 0; j < 8; j++) acc[i][j] = fmaf(wv, av[j], acc[i][j]);
        }
    }
    int ostride = TO_GMEM ? HW : LDM;
#pragma unroll
    for (int i = 0; i < 4; i++) {
        *(float4*)(outp + (oc0 + i) * ostride + w0)     = make_float4(acc[i][0], acc[i][1], acc[i][2], acc[i][3]);
        *(float4*)(outp + (oc0 + i) * ostride + w0 + 4) = make_float4(acc[i][4], acc[i][5], acc[i][6], acc[i][7]);
    }
}

// F_T[w][d] = sum_c A[c][w] * Wt[c][d] + bias[d]   (128x64 transposed output)
__device__ __forceinline__ void gemm_tr(const float* __restrict__ sWt,
                                        const float* __restrict__ sA,
                                        float* __restrict__ sFT,
                                        const float* __restrict__ bias, int tid)
{
    int w0 = (tid >> 4) << 3;
    int d0 = (tid & 15) << 2;
    float acc[8][4];
#pragma unroll
    for (int j = 0; j < 4; j++) {
        float bb = bias[d0 + j];
#pragma unroll
        for (int i = 0; i < 8; i++) acc[i][j] = bb;
    }
#pragma unroll 4
    for (int k = 0; k < 64; k++) {
        float4 a0 = *(const float4*)(sA + k * LDM + w0);
        float4 a1 = *(const float4*)(sA + k * LDM + w0 + 4);
        float av[8] = {a0.x, a0.y, a0.z, a0.w, a1.x, a1.y, a1.z, a1.w};
#pragma unroll
        for (int j = 0; j < 4; j++) {
            float wv = sWt[k * LDT + d0 + j];
#pragma unroll
            for (int i = 0; i < 8; i++) acc[i][j] = fmaf(av[i], wv, acc[i][j]);
        }
    }
#pragma unroll
    for (int i = 0; i < 8; i++)
        *(float4*)(sFT + (w0 + i) * LDT + d0) = make_float4(acc[i][0], acc[i][1], acc[i][2], acc[i][3]);
}

// St[d][c] = sum_w B[c][w] * FT[w][d]   (64x64 score, K=128, stored transposed)
__device__ __forceinline__ void gemm_score(const float* __restrict__ sB,
                                           const float* __restrict__ sFT,
                                           float* __restrict__ sSt, int tid)
{
    int c0 = (tid >> 4) << 2;
    int d0 = (tid & 15) << 2;
    float acc[4][4];
#pragma unroll
    for (int i = 0; i < 4; i++)
#pragma unroll
        for (int j = 0; j < 4; j++) acc[i][j] = 0.f;
#pragma unroll 4
    for (int k = 0; k < 128; k++) {
        float4 f = *(const float4*)(sFT + k * LDT + d0);
        float fv[4] = {f.x, f.y, f.z, f.w};
#pragma unroll
        for (int i = 0; i < 4; i++) {
            float bv = sB[(c0 + i) * LDM + k];
#pragma unroll
            for (int j = 0; j < 4; j++) acc[i][j] = fmaf(bv, fv[j], acc[i][j]);
        }
    }
#pragma unroll
    for (int i = 0; i < 4; i++)
#pragma unroll
        for (int j = 0; j < 4; j++)
            sSt[(d0 + j) * LDT + c0 + i] = acc[i][j];
}

__global__ void __launch_bounds__(256) attn_kernel(
    const float* __restrict__ x,  const float* __restrict__ xf, const float* __restrict__ xr,
    const float* __restrict__ Wx, const float* __restrict__ bx,
    const float* __restrict__ Wxf, const float* __restrict__ bxf,
    const float* __restrict__ Wxr, const float* __restrict__ bxr)
{
    extern __shared__ float smem[];
    float* sA  = smem + OFF_A;
    float* sP  = smem + OFF_P;
    float* sB1 = smem + OFF_B1;
    float* sB2 = smem + OFF_B2;
    float* sFT = smem + OFF_FT;
    float* sSt = smem + OFF_ST;
    float* sWt = smem + OFF_WT;

    int tid = threadIdx.x;
    int bh = blockIdx.x;
    int b = bh >> 7, h = bh & 127;

    // Load x tile into sA and copy x_org into concat channels [128,192)
    {
        const float* xsrc = x + (size_t)b * 64 * HW + h * NW;
        float* ydst = g_Y + ((size_t)b * NC3 + 128) * HW + h * NW;
        for (int idx = tid; idx < 8192; idx += 256) {
            int c = idx >> 7, w = idx & 127;
            float v = xsrc[c * HW + w];
            sA[c * LDM + w] = v;
            ydst[c * HW + w] = v;
        }
    }
    load_wt(sWt, Wx, tid);
    __syncthreads();

    gemm_ow<false>(sWt, sA, sP, bx, tid);          // xp
    __syncthreads();
    load_wt(sWt, g_W1f, tid);
    __syncthreads();
    gemm_ow<false>(sWt, sA, sB1, g_b1f, tid);      // x1
    __syncthreads();
    load_wt(sWt, g_W2f, tid);
    __syncthreads();
    gemm_ow<false>(sWt, sA, sB2, g_b2f, tid);      // x2
    __syncthreads();

    // ---- xf path ----
    load_tile(sA, xf, b, h, tid);
    load_wt(sWt, Wxf, tid);
    __syncthreads();
    gemm_tr(sWt, sA, sFT, bxf, tid);               // xfp^T
    __syncthreads();
    gemm_score(sB1, sFT, sSt, tid);                // score1^T
    __syncthreads();
    gemm_ow<true>(sSt, sP, g_Y + (size_t)b * NC3 * HW + h * NW, g_zero64, tid);  // feature_xf -> ch [0,64)

    // ---- xr path ----
    load_tile(sA, xr, b, h, tid);
    load_wt(sWt, Wxr, tid);
    __syncthreads();                                // also guards sSt readers above
    gemm_tr(sWt, sA, sFT, bxr, tid);               // xrp^T
    __syncthreads();
    gemm_score(sB2, sFT, sSt, tid);                // score2^T
    __syncthreads();
    gemm_ow<true>(sSt, sP, g_Y + ((size_t)b * NC3 + 64) * HW + h * NW, g_zero64, tid); // feature_xr -> ch [64,128)
}

// =================================================================
// Kernel 2: 3x3 conv 192->192 + BN + ReLU (implicit GEMM, fp32)
// =================================================================
#define ICC 16
#define SIN_LD 132
#define SW_LD 68
#define CONV_SIN_SIZE (ICC * 3 * SIN_LD)            // 6336 floats
#define CONV_SW_SIZE  (ICC * 9 * SW_LD)             // 9792 floats
#define CONV_SMEM_FLOATS (CONV_SIN_SIZE + CONV_SW_SIZE)  // 16128 floats = 64512 B

__global__ void __launch_bounds__(256, 3) conv_kernel(const float* __restrict__ Wg,
                                                      float* __restrict__ out)
{
    extern __shared__ float smem[];
    float* sIn  = smem;
    float* sWgt = smem + CONV_SIN_SIZE;

    int tid = threadIdx.x;
    int ocb = blockIdx.x * 64;       // 0, 64, 128
    int h = blockIdx.y;
    int b = blockIdx.z;
    int oc0 = (tid >> 4) << 2;       // 4 output channels / thread
    int w0  = (tid & 15) << 3;       // 8 pixels / thread

    float acc[4][8];
#pragma unroll
    for (int i = 0; i < 4; i++)
#pragma unroll
        for (int j = 0; j < 8; j++) acc[i][j] = 0.f;

    const float* Yb = g_Y + (size_t)b * NC3 * HW;

    for (int icb = 0; icb < NC3; icb += ICC) {
        // --- load input slab: ICC ic x 3 rows x 132 (wc = w+1, zero pad) ---
        for (int idx = tid; idx < CONV_SIN_SIZE; idx += 256) {
            int wc = idx % SIN_LD;
            int t = idx / SIN_LD;
            int r = t % 3, ic = t / 3;
            int hr = h + r - 1;
            int w = wc - 1;
            float v = 0.f;
            if ((unsigned)hr < 128u && (unsigned)w < 128u)
                v = Yb[(icb + ic) * HW + hr * NW + w];
            sIn[idx] = v;
        }
        // --- load weights transposed: sWgt[(ic*9+kh*3+kw)][oc] ---
        for (int idx = tid; idx < 64 * ICC * 9; idx += 256) {
            int icr = idx % (ICC * 9);
            int oc = idx / (ICC * 9);
            sWgt[icr * SW_LD + oc] = Wg[(ocb + oc) * (NC3 * 9) + icb * 9 + icr];
        }
        __syncthreads();

#pragma unroll 2
        for (int ic = 0; ic < ICC; ic++) {
#pragma unroll
            for (int kh = 0; kh < 3; kh++) {
                const float* inr = sIn + (ic * 3 + kh) * SIN_LD + w0;   // wc=w0 => w=w0-1
                float4 a0 = *(const float4*)(inr);        // w0-1..w0+2
                float4 a1 = *(const float4*)(inr + 4);    // w0+3..w0+6
                float in10[10];
                in10[0] = a0.x; in10[1] = a0.y; in10[2] = a0.z; in10[3] = a0.w;
                in10[4] = a1.x; in10[5] = a1.y; in10[6] = a1.z; in10[7] = a1.w;
                in10[8] = inr[8];                         // w0+7
                in10[9] = inr[9];                         // w0+8
                int K = ic * 9 + kh * 3;
                float4 wk0 = *(const float4*)(sWgt + K * SW_LD + oc0);
                float4 wk1 = *(const float4*)(sWgt + (K + 1) * SW_LD + oc0);
                float4 wk2 = *(const float4*)(sWgt + (K + 2) * SW_LD + oc0);
                float w0v[4] = {wk0.x, wk0.y, wk0.z, wk0.w};
                float w1v[4] = {wk1.x, wk1.y, wk1.z, wk1.w};
                float w2v[4] = {wk2.x, wk2.y, wk2.z, wk2.w};
#pragma unroll
                for (int i = 0; i < 4; i++) {
#pragma unroll
                    for (int j = 0; j < 8; j++) {
                        acc[i][j] = fmaf(w0v[i], in10[j],     acc[i][j]);
                        acc[i][j] = fmaf(w1v[i], in10[j + 1], acc[i][j]);
                        acc[i][j] = fmaf(w2v[i], in10[j + 2], acc[i][j]);
                    }
                }
            }
        }
        __syncthreads();
    }

    // --- fused BN + ReLU epilogue ---
#pragma unroll
    for (int i = 0; i < 4; i++) {
        int oc = ocb + oc0 + i;
        float al = g_alpha[oc];
        float bp = g_betap[oc];
        float4 v0, v1;
        v0.x = fmaxf(fmaf(acc[i][0], al, bp), 0.f);
        v0.y = fmaxf(fmaf(acc[i][1], al, bp), 0.f);
        v0.z = fmaxf(fmaf(acc[i][2], al, bp), 0.f);
        v0.w = fmaxf(fmaf(acc[i][3], al, bp), 0.f);
        v1.x = fmaxf(fmaf(acc[i][4], al, bp), 0.f);
        v1.y = fmaxf(fmaf(acc[i][5], al, bp), 0.f);
        v1.z = fmaxf(fmaf(acc[i][6], al, bp), 0.f);
        v1.w = fmaxf(fmaf(acc[i][7], al, bp), 0.f);
        float* op = out + ((size_t)b * NC3 + oc) * HW + h * NW + w0;
        *(float4*)(op)     = v0;
        *(float4*)(op + 4) = v1;
    }
}

// =================================================================
// launch
// =================================================================
extern "C" void kernel_launch(void* const* d_in, const int* in_sizes, int n_in,
                              void* d_out, int out_size)
{
    const float* x     = (const float*)d_in[0];
    const float* xf    = (const float*)d_in[1];
    const float* xr    = (const float*)d_in[2];
    const float* Wx    = (const float*)d_in[3];
    const float* bx    = (const float*)d_in[4];
    const float* Wx1   = (const float*)d_in[5];
    const float* bx1   = (const float*)d_in[6];
    const float* Wx2   = (const float*)d_in[7];
    const float* bx2   = (const float*)d_in[8];
    const float* Wxf   = (const float*)d_in[9];
    const float* bxf   = (const float*)d_in[10];
    const float* Wxr   = (const float*)d_in[11];
    const float* bxr   = (const float*)d_in[12];
    const float* W_msa = (const float*)d_in[13];
    const float* b_msa = (const float*)d_in[14];
    const float* gamma = (const float*)d_in[15];
    const float* beta  = (const float*)d_in[16];
    const float* mean  = (const float*)d_in[17];
    const float* var   = (const float*)d_in[18];
    float* out = (float*)d_out;

    cudaFuncSetAttribute(attn_kernel, cudaFuncAttributeMaxDynamicSharedMemorySize,
                         ATTN_SMEM_FLOATS * sizeof(float));
    cudaFuncSetAttribute(conv_kernel, cudaFuncAttributeMaxDynamicSharedMemorySize,
                         CONV_SMEM_FLOATS * sizeof(float));

    prep_kernel<<<1, 256>>>(Wx, bx, Wx1, bx1, Wx2, bx2, b_msa, gamma, beta, mean, var);

    attn_kernel<<<NB * NH, 256, ATTN_SMEM_FLOATS * sizeof(float)>>>(
        x, xf, xr, Wx, bx, Wxf, bxf, Wxr, bxr);

    conv_kernel<<<dim3(3, NH, NB), 256, CONV_SMEM_FLOATS * sizeof(float)>>>(W_msa, out);
}

// round 10
// speedup vs baseline: 2.7706x; 2.7706x over previous
#include <cuda_runtime.h>
#include <cstdint>

// Problem constants
#define NB 8
#define NC 64
#define NC3 192
#define NH 128
#define NW 128
#define HW (NH*NW)          // 16384

// ---------------- scratch (no cudaMalloc allowed) ----------------
__device__ float g_Y[(size_t)NB * NC3 * HW];   // concat buffer [b,192,h,w]  (~100.7 MB)
__device__ float g_W1f[64 * 64];
__device__ float g_W2f[64 * 64];
__device__ float g_b1f[64];
__device__ float g_b2f[64];
__device__ float g_alpha[192];
__device__ float g_betap[192];
__device__ float g_zero64[64];                 // zero-initialized

// tf32-rounded, pre-transposed conv weights, laid out exactly as the conv
// kernel's smem image: [ocb(3)][icb(12)][(kk*16+ic)*72 + oc]
#define ICC 16
#define SWT_LD 72
#define CONV_SWT (9 * ICC * SWT_LD)            // 10368 floats per (ocb,icb) slab
__device__ float g_Wt[3 * 12 * CONV_SWT];      // ~1.5 MB

__device__ __forceinline__ float tf32r(float x) {
    uint32_t u;
    asm("cvt.rna.tf32.f32 %0, %1;" : "=r"(u) : "f"(x));
    return __uint_as_float(u);
}

// =================================================================
// Kernel 0: fuse weights, BN params, and pre-transpose conv weights
// =================================================================
__global__ void prep_kernel(const float* __restrict__ Wx,  const float* __restrict__ bx,
                            const float* __restrict__ Wx1, const float* __restrict__ bx1,
                            const float* __restrict__ Wx2, const float* __restrict__ bx2,
                            const float* __restrict__ Wg,  const float* __restrict__ b_msa,
                            const float* __restrict__ gamma, const float* __restrict__ beta,
                            const float* __restrict__ mean,  const float* __restrict__ var)
{
    int tid = blockIdx.x * blockDim.x + threadIdx.x;
    int nthr = gridDim.x * blockDim.x;

    for (int idx = tid; idx < 4096; idx += nthr) {
        int o = idx >> 6, c = idx & 63;
        float s1 = 0.f, s2 = 0.f;
        for (int k = 0; k < 64; k++) {
            float wc = Wx[k * 64 + c];
            s1 = fmaf(Wx1[o * 64 + k], wc, s1);
            s2 = fmaf(Wx2[o * 64 + k], wc, s2);
        }
        g_W1f[idx] = s1;
        g_W2f[idx] = s2;
    }
    for (int o = tid; o < 64; o += nthr) {
        float s1 = bx1[o], s2 = bx2[o];
        for (int k = 0; k < 64; k++) {
            float bk = bx[k];
            s1 = fmaf(Wx1[o * 64 + k], bk, s1);
            s2 = fmaf(Wx2[o * 64 + k], bk, s2);
        }
        g_b1f[o] = s1;
        g_b2f[o] = s2;
    }
    for (int o = tid; o < 192; o += nthr) {
        float a = gamma[o] * rsqrtf(var[o] + 1e-4f);
        g_alpha[o] = a;
        g_betap[o] = fmaf(b_msa[o] - mean[o], a, beta[o]);
    }
    // conv weight transpose + tf32 rounding
    for (int idx = tid; idx < 3 * 12 * CONV_SWT; idx += nthr) {
        int ocb_i = idx / (12 * CONV_SWT);
        int rem = idx % (12 * CONV_SWT);
        int icb_i = rem / CONV_SWT;
        int s = rem % CONV_SWT;
        int row = s / SWT_LD;          // kk*16 + ic
        int oc = s % SWT_LD;
        float v = 0.f;
        if (oc < 64) {
            int kk = row >> 4, ic = row & 15;
            v = tf32r(Wg[(size_t)(ocb_i * 64 + oc) * (NC3 * 9) + (icb_i * 16 + ic) * 9 + kk]);
        }
        g_Wt[idx] = v;
    }
}

// =================================================================
// Kernel 1: per-(b,h) attention stage, all GEMMs in shared memory
// =================================================================
#define LDM 132   // stride of 64x128 matrices (float4-aligned, bank-staggered)
#define LDT 68    // stride of transposed [k][o] matrices

#define OFF_A  0
#define OFF_P  (64 * LDM)
#define OFF_B1 (2 * 64 * LDM)
#define OFF_B2 (3 * 64 * LDM)
#define OFF_FT (4 * 64 * LDM)                  // 128 x LDT
#define OFF_ST (OFF_FT + 128 * LDT)            // 64 x LDT
#define OFF_WT (OFF_ST + 64 * LDT)             // 64 x LDT
#define ATTN_SMEM_FLOATS (OFF_WT + 64 * LDT)   // 51200 floats = 204800 B

__device__ __forceinline__ void load_wt(float* sWt, const float* __restrict__ G, int tid)
{
    for (int idx = tid; idx < 4096; idx += 256) {
        int o = idx >> 6, k = idx & 63;
        sWt[k * LDT + o] = G[idx];
    }
}

__device__ __forceinline__ void load_tile(float* sA, const float* __restrict__ X,
                                          int b, int h, int tid)
{
    const float* src = X + (size_t)b * 64 * HW + h * NW;
    for (int idx = tid; idx < 8192; idx += 256) {
        int c = idx >> 7, w = idx & 127;
        sA[c * LDM + w] = src[c * HW + w];
    }
}

template <bool TO_GMEM>
__device__ __forceinline__ void gemm_ow(const float* __restrict__ sWt,
                                        const float* __restrict__ sA,
                                        float* __restrict__ outp,
                                        const float* __restrict__ bias, int tid)
{
    int oc0 = (tid >> 4) << 2;
    int w0  = (tid & 15) << 3;
    float acc[4][8];
#pragma unroll
    for (int i = 0; i < 4; i++) {
        float bb = bias[oc0 + i];
#pragma unroll
        for (int j = 0; j < 8; j++) acc[i][j] = bb;
    }
#pragma unroll 4
    for (int k = 0; k < 64; k++) {
        float4 a0 = *(const float4*)(sA + k * LDM + w0);
        float4 a1 = *(const float4*)(sA + k * LDM + w0 + 4);
        float av[8] = {a0.x, a0.y, a0.z, a0.w, a1.x, a1.y, a1.z, a1.w};
#pragma unroll
        for (int i = 0; i < 4; i++) {
            float wv = sWt[k * LDT + oc0 + i];
#pragma unroll
            for (int j = 0; j < 8; j++) acc[i][j] = fmaf(wv, av[j], acc[i][j]);
        }
    }
    int ostride = TO_GMEM ? HW : LDM;
#pragma unroll
    for (int i = 0; i < 4; i++) {
        *(float4*)(outp + (oc0 + i) * ostride + w0)     = make_float4(acc[i][0], acc[i][1], acc[i][2], acc[i][3]);
        *(float4*)(outp + (oc0 + i) * ostride + w0 + 4) = make_float4(acc[i][4], acc[i][5], acc[i][6], acc[i][7]);
    }
}

__device__ __forceinline__ void gemm_tr(const float* __restrict__ sWt,
                                        const float* __restrict__ sA,
                                        float* __restrict__ sFT,
                                        const float* __restrict__ bias, int tid)
{
    int w0 = (tid >> 4) << 3;
    int d0 = (tid & 15) << 2;
    float acc[8][4];
#pragma unroll
    for (int j = 0; j < 4; j++) {
        float bb = bias[d0 + j];
#pragma unroll
        for (int i = 0; i < 8; i++) acc[i][j] = bb;
    }
#pragma unroll 4
    for (int k = 0; k < 64; k++) {
        float4 a0 = *(const float4*)(sA + k * LDM + w0);
        float4 a1 = *(const float4*)(sA + k * LDM + w0 + 4);
        float av[8] = {a0.x, a0.y, a0.z, a0.w, a1.x, a1.y, a1.z, a1.w};
#pragma unroll
        for (int j = 0; j < 4; j++) {
            float wv = sWt[k * LDT + d0 + j];
#pragma unroll
            for (int i = 0; i < 8; i++) acc[i][j] = fmaf(av[i], wv, acc[i][j]);
        }
    }
#pragma unroll
    for (int i = 0; i < 8; i++)
        *(float4*)(sFT + (w0 + i) * LDT + d0) = make_float4(acc[i][0], acc[i][1], acc[i][2], acc[i][3]);
}

__device__ __forceinline__ void gemm_score(const float* __restrict__ sB,
                                           const float* __restrict__ sFT,
                                           float* __restrict__ sSt, int tid)
{
    int c0 = (tid >> 4) << 2;
    int d0 = (tid & 15) << 2;
    float acc[4][4];
#pragma unroll
    for (int i = 0; i < 4; i++)
#pragma unroll
        for (int j = 0; j < 4; j++) acc[i][j] = 0.f;
#pragma unroll 4
    for (int k = 0; k < 128; k++) {
        float4 f = *(const float4*)(sFT + k * LDT + d0);
        float fv[4] = {f.x, f.y, f.z, f.w};
#pragma unroll
        for (int i = 0; i < 4; i++) {
            float bv = sB[(c0 + i) * LDM + k];
#pragma unroll
            for (int j = 0; j < 4; j++) acc[i][j] = fmaf(bv, fv[j], acc[i][j]);
        }
    }
#pragma unroll
    for (int i = 0; i < 4; i++)
#pragma unroll
        for (int j = 0; j < 4; j++)
            sSt[(d0 + j) * LDT + c0 + i] = acc[i][j];
}

__global__ void __launch_bounds__(256) attn_kernel(
    const float* __restrict__ x,  const float* __restrict__ xf, const float* __restrict__ xr,
    const float* __restrict__ Wx, const float* __restrict__ bx,
    const float* __restrict__ Wxf, const float* __restrict__ bxf,
    const float* __restrict__ Wxr, const float* __restrict__ bxr)
{
    extern __shared__ float smem[];
    float* sA  = smem + OFF_A;
    float* sP  = smem + OFF_P;
    float* sB1 = smem + OFF_B1;
    float* sB2 = smem + OFF_B2;
    float* sFT = smem + OFF_FT;
    float* sSt = smem + OFF_ST;
    float* sWt = smem + OFF_WT;

    int tid = threadIdx.x;
    int bh = blockIdx.x;
    int b = bh >> 7, h = bh & 127;

    {
        const float* xsrc = x + (size_t)b * 64 * HW + h * NW;
        float* ydst = g_Y + ((size_t)b * NC3 + 128) * HW + h * NW;
        for (int idx = tid; idx < 8192; idx += 256) {
            int c = idx >> 7, w = idx & 127;
            float v = xsrc[c * HW + w];
            sA[c * LDM + w] = v;
            ydst[c * HW + w] = v;
        }
    }
    load_wt(sWt, Wx, tid);
    __syncthreads();

    gemm_ow<false>(sWt, sA, sP, bx, tid);          // xp
    __syncthreads();
    load_wt(sWt, g_W1f, tid);
    __syncthreads();
    gemm_ow<false>(sWt, sA, sB1, g_b1f, tid);      // x1
    __syncthreads();
    load_wt(sWt, g_W2f, tid);
    __syncthreads();
    gemm_ow<false>(sWt, sA, sB2, g_b2f, tid);      // x2
    __syncthreads();

    // ---- xf path ----
    load_tile(sA, xf, b, h, tid);
    load_wt(sWt, Wxf, tid);
    __syncthreads();
    gemm_tr(sWt, sA, sFT, bxf, tid);               // xfp^T
    __syncthreads();
    gemm_score(sB1, sFT, sSt, tid);                // score1^T
    __syncthreads();
    gemm_ow<true>(sSt, sP, g_Y + (size_t)b * NC3 * HW + h * NW, g_zero64, tid);

    // ---- xr path ----
    load_tile(sA, xr, b, h, tid);
    load_wt(sWt, Wxr, tid);
    __syncthreads();
    gemm_tr(sWt, sA, sFT, bxr, tid);               // xrp^T
    __syncthreads();
    gemm_score(sB2, sFT, sSt, tid);                // score2^T
    __syncthreads();
    gemm_ow<true>(sSt, sP, g_Y + ((size_t)b * NC3 + 64) * HW + h * NW, g_zero64, tid);
}

// =================================================================
// Kernel 2: 3x3 conv 192->192 + BN + ReLU, tf32 tensor-core implicit GEMM
// =================================================================
#define SIN_LD 132
#define CONV_SIN (ICC * 3 * SIN_LD)                 // 6336 floats
#define CONV_SMEM (CONV_SIN + CONV_SWT)             // 16704 floats = 66816 B

__device__ __forceinline__ void mma_tf32(float4& c, const uint32_t* a, const uint32_t* b)
{
    asm volatile("mma.sync.aligned.m16n8k8.row.col.f32.tf32.tf32.f32 "
                 "{%0,%1,%2,%3}, {%4,%5,%6,%7}, {%8,%9}, {%0,%1,%2,%3};"
                 : "+f"(c.x), "+f"(c.y), "+f"(c.z), "+f"(c.w)
                 : "r"(a[0]), "r"(a[1]), "r"(a[2]), "r"(a[3]), "r"(b[0]), "r"(b[1]));
}

__global__ void __launch_bounds__(256, 2) conv_mma_kernel(float* __restrict__ out)
{
    extern __shared__ float smem[];
    float* sIn = smem;
    float* sW  = smem + CONV_SIN;

    int tid = threadIdx.x;
    int lane = tid & 31, warp = tid >> 5;
    int ocb = blockIdx.x;            // 0..2 (x64)
    int h = blockIdx.y;
    int b = blockIdx.z;
    int warp_oc = (warp >> 2) * 32;  // 0 or 32
    int warp_w  = (warp & 3) * 32;   // 0..96
    int g = lane >> 2, r = lane & 3; // group / thread-in-group

    float4 Cacc[2][4];
#pragma unroll
    for (int mi = 0; mi < 2; mi++)
#pragma unroll
        for (int nj = 0; nj < 4; nj++) Cacc[mi][nj] = make_float4(0.f, 0.f, 0.f, 0.f);

    const float* Yb = g_Y + (size_t)b * NC3 * HW;
    const float* WtB = g_Wt + (size_t)ocb * 12 * CONV_SWT;

    for (int chunk = 0; chunk < 12; chunk++) {
        int icb = chunk * ICC;
        // --- stage input slab (tf32-rounded): ICC ic x 3 rows x 132 ---
        for (int idx = tid; idx < CONV_SIN; idx += 256) {
            int wc = idx % SIN_LD;
            int t = idx / SIN_LD;
            int rr = t % 3, ic = t / 3;
            int hr = h + rr - 1;
            int w = wc - 1;
            float v = 0.f;
            if ((unsigned)hr < 128u && (unsigned)w < 128u)
                v = Yb[(icb + ic) * HW + hr * NW + w];
            sIn[idx] = tf32r(v);
        }
        // --- stage pre-transposed weights: straight vectorized copy ---
        {
            const float4* src = (const float4*)(WtB + (size_t)chunk * CONV_SWT);
            float4* dst = (float4*)sW;
            for (int idx = tid; idx < CONV_SWT / 4; idx += 256)
                dst[idx] = src[idx];
        }
        __syncthreads();

#pragma unroll
        for (int kk = 0; kk < 9; kk++) {
            int kh = kk / 3, kw = kk % 3;
            const float* inb = sIn + kh * SIN_LD + warp_w + kw;
            const float* wb  = sW + kk * ICC * SWT_LD + warp_oc;
#pragma unroll
            for (int ic0 = 0; ic0 < ICC; ic0 += 8) {
                uint32_t afr[2][4];
                uint32_t bfr[4][2];
#pragma unroll
                for (int mi = 0; mi < 2; mi++) {
                    const float* wa = wb + mi * 16 + g;
                    afr[mi][0] = __float_as_uint(wa[(ic0 + r) * SWT_LD]);
                    afr[mi][1] = __float_as_uint(wa[(ic0 + r) * SWT_LD + 8]);
                    afr[mi][2] = __float_as_uint(wa[(ic0 + r + 4) * SWT_LD]);
                    afr[mi][3] = __float_as_uint(wa[(ic0 + r + 4) * SWT_LD + 8]);
                }
#pragma unroll
                for (int nj = 0; nj < 4; nj++) {
                    const float* ib = inb + nj * 8 + g;
                    bfr[nj][0] = __float_as_uint(ib[(ic0 + r) * 3 * SIN_LD]);
                    bfr[nj][1] = __float_as_uint(ib[(ic0 + r + 4) * 3 * SIN_LD]);
                }
#pragma unroll
                for (int mi = 0; mi < 2; mi++)
#pragma unroll
                    for (int nj = 0; nj < 4; nj++)
                        mma_tf32(Cacc[mi][nj], afr[mi], bfr[nj]);
            }
        }
        __syncthreads();
    }

    // --- fused BN + ReLU epilogue ---
#pragma unroll
    for (int mi = 0; mi < 2; mi++) {
        int oc_lo = ocb * 64 + warp_oc + mi * 16 + g;
        int oc_hi = oc_lo + 8;
        float al0 = g_alpha[oc_lo], bp0 = g_betap[oc_lo];
        float al1 = g_alpha[oc_hi], bp1 = g_betap[oc_hi];
        float* row0 = out + ((size_t)b * NC3 + oc_lo) * HW + h * NW;
        float* row1 = out + ((size_t)b * NC3 + oc_hi) * HW + h * NW;
#pragma unroll
        for (int nj = 0; nj < 4; nj++) {
            int w = warp_w + nj * 8 + 2 * r;
            float2 v0, v1;
            v0.x = fmaxf(fmaf(Cacc[mi][nj].x, al0, bp0), 0.f);
            v0.y = fmaxf(fmaf(Cacc[mi][nj].y, al0, bp0), 0.f);
            v1.x = fmaxf(fmaf(Cacc[mi][nj].z, al1, bp1), 0.f);
            v1.y = fmaxf(fmaf(Cacc[mi][nj].w, al1, bp1), 0.f);
            *(float2*)(row0 + w) = v0;
            *(float2*)(row1 + w) = v1;
        }
    }
}

// =================================================================
// launch
// =================================================================
extern "C" void kernel_launch(void* const* d_in, const int* in_sizes, int n_in,
                              void* d_out, int out_size)
{
    const float* x     = (const float*)d_in[0];
    const float* xf    = (const float*)d_in[1];
    const float* xr    = (const float*)d_in[2];
    const float* Wx    = (const float*)d_in[3];
    const float* bx    = (const float*)d_in[4];
    const float* Wx1   = (const float*)d_in[5];
    const float* bx1   = (const float*)d_in[6];
    const float* Wx2   = (const float*)d_in[7];
    const float* bx2   = (const float*)d_in[8];
    const float* Wxf   = (const float*)d_in[9];
    const float* bxf   = (const float*)d_in[10];
    const float* Wxr   = (const float*)d_in[11];
    const float* bxr   = (const float*)d_in[12];
    const float* W_msa = (const float*)d_in[13];
    const float* b_msa = (const float*)d_in[14];
    const float* gamma = (const float*)d_in[15];
    const float* beta  = (const float*)d_in[16];
    const float* mean  = (const float*)d_in[17];
    const float* var   = (const float*)d_in[18];
    float* out = (float*)d_out;

    cudaFuncSetAttribute(attn_kernel, cudaFuncAttributeMaxDynamicSharedMemorySize,
                         ATTN_SMEM_FLOATS * sizeof(float));
    cudaFuncSetAttribute(conv_mma_kernel, cudaFuncAttributeMaxDynamicSharedMemorySize,
                         CONV_SMEM * sizeof(float));

    prep_kernel<<<128, 256>>>(Wx, bx, Wx1, bx1, Wx2, bx2, W_msa, b_msa,
                              gamma, beta, mean, var);

    attn_kernel<<<NB * NH, 256, ATTN_SMEM_FLOATS * sizeof(float)>>>(
        x, xf, xr, Wx, bx, Wxf, bxf, Wxr, bxr);

    conv_mma_kernel<<<dim3(3, NH, NB), 256, CONV_SMEM * sizeof(float)>>>(out);
}

// round 12
// speedup vs baseline: 2.8864x; 1.0418x over previous
#include <cuda_runtime.h>
#include <cuda_fp16.h>
#include <cstdint>

// Problem constants
#define NB 8
#define NC 64
#define NC3 192
#define NH 128
#define NW 128
#define HW (NH*NW)          // 16384

// ---------------- scratch (no cudaMalloc allowed) ----------------
__device__ float g_Y[(size_t)NB * NC3 * HW];   // concat buffer [b,192,h,w]  (~100.7 MB)
__device__ float g_W1f[64 * 64];
__device__ float g_W2f[64 * 64];
__device__ float g_b1f[64];
__device__ float g_b2f[64];
__device__ float g_alpha[192];
__device__ float g_betap[192];
__device__ float g_zero64[64];                 // zero-initialized

// fp16 conv weights as half2 (ic-pairs), laid out exactly as the conv smem image:
// [ocb(3)][chunk(12)][kk(9)][ic2(8)][oc pad 72]
#define ICC 16
#define SW_PAD 72
#define CONV_SW2 (9 * 8 * SW_PAD)              // 5184 u32 per (ocb,chunk) slab
__device__ uint32_t g_Wh[3 * 12 * CONV_SW2];   // ~747 KB

// =================================================================
// Kernel 0: fuse weights, BN params, pack fp16 conv weights
// =================================================================
__global__ void prep_kernel(const float* __restrict__ Wx,  const float* __restrict__ bx,
                            const float* __restrict__ Wx1, const float* __restrict__ bx1,
                            const float* __restrict__ Wx2, const float* __restrict__ bx2,
                            const float* __restrict__ Wg,  const float* __restrict__ b_msa,
                            const float* __restrict__ gamma, const float* __restrict__ beta,
                            const float* __restrict__ mean,  const float* __restrict__ var)
{
    int tid = blockIdx.x * blockDim.x + threadIdx.x;
    int nthr = gridDim.x * blockDim.x;

    for (int idx = tid; idx < 4096; idx += nthr) {
        int o = idx >> 6, c = idx & 63;
        float s1 = 0.f, s2 = 0.f;
        for (int k = 0; k < 64; k++) {
            float wc = Wx[k * 64 + c];
            s1 = fmaf(Wx1[o * 64 + k], wc, s1);
            s2 = fmaf(Wx2[o * 64 + k], wc, s2);
        }
        g_W1f[idx] = s1;
        g_W2f[idx] = s2;
    }
    for (int o = tid; o < 64; o += nthr) {
        float s1 = bx1[o], s2 = bx2[o];
        for (int k = 0; k < 64; k++) {
            float bk = bx[k];
            s1 = fmaf(Wx1[o * 64 + k], bk, s1);
            s2 = fmaf(Wx2[o * 64 + k], bk, s2);
        }
        g_b1f[o] = s1;
        g_b2f[o] = s2;
    }
    for (int o = tid; o < 192; o += nthr) {
        float a = gamma[o] * rsqrtf(var[o] + 1e-4f);
        g_alpha[o] = a;
        g_betap[o] = fmaf(b_msa[o] - mean[o], a, beta[o]);
    }
    // fp16 conv weight pack: half2 = (ic even, ic odd), transposed to [.. ][oc]
    for (int idx = tid; idx < 3 * 12 * CONV_SW2; idx += nthr) {
        int ocb_i = idx / (12 * CONV_SW2);
        int rem = idx % (12 * CONV_SW2);
        int chunk = rem / CONV_SW2;
        int s = rem % CONV_SW2;
        int kk = s / (8 * SW_PAD);
        int s2 = s % (8 * SW_PAD);
        int ic2 = s2 / SW_PAD;
        int oc = s2 % SW_PAD;
        uint32_t v = 0;
        if (oc < 64) {
            const float* wp = Wg + (size_t)(ocb_i * 64 + oc) * (NC3 * 9)
                              + (chunk * ICC + 2 * ic2) * 9 + kk;
            __half2 hv = __floats2half2_rn(wp[0], wp[9]);   // ic, ic+1 (stride 9 over taps)
            v = *(uint32_t*)&hv;
        }
        g_Wh[idx] = v;
    }
}

// =================================================================
// Kernel 1: per-(b,h) attention stage, all GEMMs in shared memory
// =================================================================
#define LDM 132   // stride of 64x128 matrices (float4-aligned, bank-staggered)
#define LDT 68    // stride of transposed [k][o] matrices

#define OFF_A  0
#define OFF_P  (64 * LDM)
#define OFF_B1 (2 * 64 * LDM)
#define OFF_B2 (3 * 64 * LDM)
#define OFF_FT (4 * 64 * LDM)                  // 128 x LDT
#define OFF_ST (OFF_FT + 128 * LDT)            // 64 x LDT
#define OFF_WT (OFF_ST + 64 * LDT)             // 64 x LDT
#define ATTN_SMEM_FLOATS (OFF_WT + 64 * LDT)   // 51200 floats = 204800 B

__device__ __forceinline__ void load_wt(float* sWt, const float* __restrict__ G, int tid)
{
    for (int idx = tid; idx < 4096; idx += 256) {
        int o = idx >> 6, k = idx & 63;
        sWt[k * LDT + o] = G[idx];
    }
}

__device__ __forceinline__ void load_tile(float* sA, const float* __restrict__ X,
                                          int b, int h, int tid)
{
    const float* src = X + (size_t)b * 64 * HW + h * NW;
    for (int idx = tid; idx < 8192; idx += 256) {
        int c = idx >> 7, w = idx & 127;
        sA[c * LDM + w] = src[c * HW + w];
    }
}

template <bool TO_GMEM>
__device__ __forceinline__ void gemm_ow(const float* __restrict__ sWt,
                                        const float* __restrict__ sA,
                                        float* __restrict__ outp,
                                        const float* __restrict__ bias, int tid)
{
    int oc0 = (tid >> 4) << 2;
    int w0  = (tid & 15) << 3;
    float acc[4][8];
#pragma unroll
    for (int i = 0; i < 4; i++) {
        float bb = bias[oc0 + i];
#pragma unroll
        for (int j = 0; j < 8; j++) acc[i][j] = bb;
    }
#pragma unroll 4
    for (int k = 0; k < 64; k++) {
        float4 a0 = *(const float4*)(sA + k * LDM + w0);
        float4 a1 = *(const float4*)(sA + k * LDM + w0 + 4);
        float av[8] = {a0.x, a0.y, a0.z, a0.w, a1.x, a1.y, a1.z, a1.w};
#pragma unroll
        for (int i = 0; i < 4; i++) {
            float wv = sWt[k * LDT + oc0 + i];
#pragma unroll
            for (int j = 0; j < 8; j++) acc[i][j] = fmaf(wv, av[j], acc[i][j]);
        }
    }
    int ostride = TO_GMEM ? HW : LDM;
#pragma unroll
    for (int i = 0; i < 4; i++) {
        *(float4*)(outp + (oc0 + i) * ostride + w0)     = make_float4(acc[i][0], acc[i][1], acc[i][2], acc[i][3]);
        *(float4*)(outp + (oc0 + i) * ostride + w0 + 4) = make_float4(acc[i][4], acc[i][5], acc[i][6], acc[i][7]);
    }
}

__device__ __forceinline__ void gemm_tr(const float* __restrict__ sWt,
                                        const float* __restrict__ sA,
                                        float* __restrict__ sFT,
                                        const float* __restrict__ bias, int tid)
{
    int w0 = (tid >> 4) << 3;
    int d0 = (tid & 15) << 2;
    float acc[8][4];
#pragma unroll
    for (int j = 0; j < 4; j++) {
        float bb = bias[d0 + j];
#pragma unroll
        for (int i = 0; i < 8; i++) acc[i][j] = bb;
    }
#pragma unroll 4
    for (int k = 0; k < 64; k++) {
        float4 a0 = *(const float4*)(sA + k * LDM + w0);
        float4 a1 = *(const float4*)(sA + k * LDM + w0 + 4);
        float av[8] = {a0.x, a0.y, a0.z, a0.w, a1.x, a1.y, a1.z, a1.w};
#pragma unroll
        for (int j = 0; j < 4; j++) {
            float wv = sWt[k * LDT + d0 + j];
#pragma unroll
            for (int i = 0; i < 8; i++) acc[i][j] = fmaf(av[i], wv, acc[i][j]);
        }
    }
#pragma unroll
    for (int i = 0; i < 8; i++)
        *(float4*)(sFT + (w0 + i) * LDT + d0) = make_float4(acc[i][0], acc[i][1], acc[i][2], acc[i][3]);
}

__device__ __forceinline__ void gemm_score(const float* __restrict__ sB,
                                           const float* __restrict__ sFT,
                                           float* __restrict__ sSt, int tid)
{
    int c0 = (tid >> 4) << 2;
    int d0 = (tid & 15) << 2;
    float acc[4][4];
#pragma unroll
    for (int i = 0; i < 4; i++)
#pragma unroll
        for (int j = 0; j < 4; j++) acc[i][j] = 0.f;
#pragma unroll 4
    for (int k = 0; k < 128; k++) {
        float4 f = *(const float4*)(sFT + k * LDT + d0);
        float fv[4] = {f.x, f.y, f.z, f.w};
#pragma unroll
        for (int i = 0; i < 4; i++) {
            float bv = sB[(c0 + i) * LDM + k];
#pragma unroll
            for (int j = 0; j < 4; j++) acc[i][j] = fmaf(bv, fv[j], acc[i][j]);
        }
    }
#pragma unroll
    for (int i = 0; i < 4; i++)
#pragma unroll
        for (int j = 0; j < 4; j++)
            sSt[(d0 + j) * LDT + c0 + i] = acc[i][j];
}

__global__ void __launch_bounds__(256) attn_kernel(
    const float* __restrict__ x,  const float* __restrict__ xf, const float* __restrict__ xr,
    const float* __restrict__ Wx, const float* __restrict__ bx,
    const float* __restrict__ Wxf, const float* __restrict__ bxf,
    const float* __restrict__ Wxr, const float* __restrict__ bxr)
{
    extern __shared__ float smem[];
    float* sA  = smem + OFF_A;
    float* sP  = smem + OFF_P;
    float* sB1 = smem + OFF_B1;
    float* sB2 = smem + OFF_B2;
    float* sFT = smem + OFF_FT;
    float* sSt = smem + OFF_ST;
    float* sWt = smem + OFF_WT;

    int tid = threadIdx.x;
    int bh = blockIdx.x;
    int b = bh >> 7, h = bh & 127;

    {
        const float* xsrc = x + (size_t)b * 64 * HW + h * NW;
        float* ydst = g_Y + ((size_t)b * NC3 + 128) * HW + h * NW;
        for (int idx = tid; idx < 8192; idx += 256) {
            int c = idx >> 7, w = idx & 127;
            float v = xsrc[c * HW + w];
            sA[c * LDM + w] = v;
            ydst[c * HW + w] = v;
        }
    }
    load_wt(sWt, Wx, tid);
    __syncthreads();

    gemm_ow<false>(sWt, sA, sP, bx, tid);          // xp
    __syncthreads();
    load_wt(sWt, g_W1f, tid);
    __syncthreads();
    gemm_ow<false>(sWt, sA, sB1, g_b1f, tid);      // x1
    __syncthreads();
    load_wt(sWt, g_W2f, tid);
    __syncthreads();
    gemm_ow<false>(sWt, sA, sB2, g_b2f, tid);      // x2
    __syncthreads();

    // ---- xf path ----
    load_tile(sA, xf, b, h, tid);
    load_wt(sWt, Wxf, tid);
    __syncthreads();
    gemm_tr(sWt, sA, sFT, bxf, tid);               // xfp^T
    __syncthreads();
    gemm_score(sB1, sFT, sSt, tid);                // score1^T
    __syncthreads();
    gemm_ow<true>(sSt, sP, g_Y + (size_t)b * NC3 * HW + h * NW, g_zero64, tid);

    // ---- xr path ----
    load_tile(sA, xr, b, h, tid);
    load_wt(sWt, Wxr, tid);
    __syncthreads();
    gemm_tr(sWt, sA, sFT, bxr, tid);               // xrp^T
    __syncthreads();
    gemm_score(sB2, sFT, sSt, tid);                // score2^T
    __syncthreads();
    gemm_ow<true>(sSt, sP, g_Y + ((size_t)b * NC3 + 64) * HW + h * NW, g_zero64, tid);
}

// =================================================================
// Kernel 2: 3x3 conv 192->192 + BN + ReLU, fp16 tensor-core implicit GEMM
//   A = weights [oc(64)][ic(16)], B = input [ic][w], fp32 accumulate
//   m16n8k16: per tap 16 LDS32 feed 8 MMAs (K=16)
// =================================================================
#define LDI 136                                   // half2 words per slab row
#define CONV_SIN2 (8 * 3 * LDI)                   // 3264 u32 (13 KB)
#define CONV_SMEM_U32 (CONV_SIN2 + CONV_SW2)      // 8448 u32 = 33792 B

__device__ __forceinline__ void mma_f16(float4& c, const uint32_t* a, const uint32_t* b)
{
    asm volatile("mma.sync.aligned.m16n8k16.row.col.f32.f16.f16.f32 "
                 "{%0,%1,%2,%3}, {%4,%5,%6,%7}, {%8,%9}, {%0,%1,%2,%3};"
                 : "+f"(c.x), "+f"(c.y), "+f"(c.z), "+f"(c.w)
                 : "r"(a[0]), "r"(a[1]), "r"(a[2]), "r"(a[3]), "r"(b[0]), "r"(b[1]));
}

__global__ void __launch_bounds__(256, 3) conv_mma_kernel(float* __restrict__ out)
{
    extern __shared__ uint32_t csmem[];
    uint32_t* sIn = csmem;                 // [ic2(8)][3 rows][LDI]  half2
    uint32_t* sW  = csmem + CONV_SIN2;     // [kk(9)][ic2(8)][SW_PAD] half2

    int tid = threadIdx.x;
    int lane = tid & 31, warp = tid >> 5;
    int ocb = blockIdx.x;            // 0..2 (x64)
    int h = blockIdx.y;
    int b = blockIdx.z;
    int warp_oc = (warp >> 2) * 32;  // 0 or 32
    int warp_w  = (warp & 3) * 32;   // 0..96
    int g = lane >> 2, r = lane & 3; // group / thread-in-group

    float4 Cacc[2][4];
#pragma unroll
    for (int mi = 0; mi < 2; mi++)
#pragma unroll
        for (int nj = 0; nj < 4; nj++) Cacc[mi][nj] = make_float4(0.f, 0.f, 0.f, 0.f);

    const float* Yb = g_Y + (size_t)b * NC3 * HW;
    const uint32_t* WhB = g_Wh + (size_t)ocb * 12 * CONV_SW2;

    for (int chunk = 0; chunk < 12; chunk++) {
        int icb = chunk * ICC;
        // --- stage input slab as half2 (ic pair): 8 ic2 x 3 rows x 132 valid cols ---
        for (int idx = tid; idx < 8 * 3 * 132; idx += 256) {
            int wc = idx % 132;
            int t = idx / 132;
            int rr = t % 3, ic2 = t / 3;
            int hr = h + rr - 1;
            int w = wc - 1;
            float lo = 0.f, hi = 0.f;
            if ((unsigned)hr < 128u && (unsigned)w < 128u) {
                const float* p = Yb + (icb + 2 * ic2) * HW + hr * NW + w;
                lo = p[0];
                hi = p[HW];
            }
            __half2 hv = __floats2half2_rn(lo, hi);
            sIn[ic2 * (3 * LDI) + rr * LDI + wc] = *(uint32_t*)&hv;
        }
        // --- stage weights: straight vectorized copy ---
        {
            const uint4* src = (const uint4*)(WhB + (size_t)chunk * CONV_SW2);
            uint4* dst = (uint4*)sW;
            for (int idx = tid; idx < CONV_SW2 / 4; idx += 256)
                dst[idx] = src[idx];
        }
        __syncthreads();

#pragma unroll
        for (int kk = 0; kk < 9; kk++) {
            int kh = kk / 3, kw = kk % 3;
            const uint32_t* wb = sW + kk * (8 * SW_PAD) + warp_oc + g;
            const uint32_t* ib = sIn + kh * LDI + warp_w + g + kw;
            uint32_t afr[2][4];
            uint32_t bfr[4][2];
#pragma unroll
            for (int mi = 0; mi < 2; mi++) {
                const uint32_t* wa = wb + mi * 16;
                afr[mi][0] = wa[r * SW_PAD];
                afr[mi][1] = wa[r * SW_PAD + 8];
                afr[mi][2] = wa[(r + 4) * SW_PAD];
                afr[mi][3] = wa[(r + 4) * SW_PAD + 8];
            }
#pragma unroll
            for (int nj = 0; nj < 4; nj++) {
                bfr[nj][0] = ib[r * (3 * LDI) + nj * 8];
                bfr[nj][1] = ib[(r + 4) * (3 * LDI) + nj * 8];
            }
#pragma unroll
            for (int mi = 0; mi < 2; mi++)
#pragma unroll
                for (int nj = 0; nj < 4; nj++)
                    mma_f16(Cacc[mi][nj], afr[mi], bfr[nj]);
        }
        __syncthreads();
    }

    // --- fused BN + ReLU epilogue ---
#pragma unroll
    for (int mi = 0; mi < 2; mi++) {
        int oc_lo = ocb * 64 + warp_oc + mi * 16 + g;
        int oc_hi = oc_lo + 8;
        float al0 = g_alpha[oc_lo], bp0 = g_betap[oc_lo];
        float al1 = g_alpha[oc_hi], bp1 = g_betap[oc_hi];
        float* row0 = out + ((size_t)b * NC3 + oc_lo) * HW + h * NW;
        float* row1 = out + ((size_t)b * NC3 + oc_hi) * HW + h * NW;
#pragma unroll
        for (int nj = 0; nj < 4; nj++) {
            int w = warp_w + nj * 8 + 2 * r;
            float2 v0, v1;
            v0.x = fmaxf(fmaf(Cacc[mi][nj].x, al0, bp0), 0.f);
            v0.y = fmaxf(fmaf(Cacc[mi][nj].y, al0, bp0), 0.f);
            v1.x = fmaxf(fmaf(Cacc[mi][nj].z, al1, bp1), 0.f);
            v1.y = fmaxf(fmaf(Cacc[mi][nj].w, al1, bp1), 0.f);
            *(float2*)(row0 + w) = v0;
            *(float2*)(row1 + w) = v1;
        }
    }
}

// =================================================================
// launch
// =================================================================
extern "C" void kernel_launch(void* const* d_in, const int* in_sizes, int n_in,
                              void* d_out, int out_size)
{
    const float* x     = (const float*)d_in[0];
    const float* xf    = (const float*)d_in[1];
    const float* xr    = (const float*)d_in[2];
    const float* Wx    = (const float*)d_in[3];
    const float* bx    = (const float*)d_in[4];
    const float* Wx1   = (const float*)d_in[5];
    const float* bx1   = (const float*)d_in[6];
    const float* Wx2   = (const float*)d_in[7];
    const float* bx2   = (const float*)d_in[8];
    const float* Wxf   = (const float*)d_in[9];
    const float* bxf   = (const float*)d_in[10];
    const float* Wxr   = (const float*)d_in[11];
    const float* bxr   = (const float*)d_in[12];
    const float* W_msa = (const float*)d_in[13];
    const float* b_msa = (const float*)d_in[14];
    const float* gamma = (const float*)d_in[15];
    const float* beta  = (const float*)d_in[16];
    const float* mean  = (const float*)d_in[17];
    const float* var   = (const float*)d_in[18];
    float* out = (float*)d_out;

    cudaFuncSetAttribute(attn_kernel, cudaFuncAttributeMaxDynamicSharedMemorySize,
                         ATTN_SMEM_FLOATS * sizeof(float));
    cudaFuncSetAttribute(conv_mma_kernel, cudaFuncAttributeMaxDynamicSharedMemorySize,
                         CONV_SMEM_U32 * sizeof(uint32_t));

    prep_kernel<<<128, 256>>>(Wx, bx, Wx1, bx1, Wx2, bx2, W_msa, b_msa,
                              gamma, beta, mean, var);

    attn_kernel<<<NB * NH, 256, ATTN_SMEM_FLOATS * sizeof(float)>>>(
        x, xf, xr, Wx, bx, Wxf, bxf, Wxr, bxr);

    conv_mma_kernel<<<dim3(3, NH, NB), 256, CONV_SMEM_U32 * sizeof(uint32_t)>>>(out);
}

// round 14
// speedup vs baseline: 4.9819x; 1.7260x over previous
#include <cuda_runtime.h>
#include <cuda_fp16.h>
#include <cstdint>

// Problem constants
#define NB 8
#define NC 64
#define NC3 192
#define NH 128
#define NW 128
#define HW (NH*NW)          // 16384

// tcgen05 availability: only when this compile pass targets sm_103a/sm_100a
#if defined(__CUDA_ARCH__) && (defined(__CUDA_ARCH_FEAT_SM103_ALL) || defined(__CUDA_ARCH_FEAT_SM100_ALL))
#define HAS_TCGEN05 1
#else
#define HAS_TCGEN05 0
#endif

// ---------------- scratch (no cudaMalloc allowed) ----------------
// Transposed fp16 concat buffer: [b][h][w][192]  (ic contiguous)  ~50.3 MB
__device__ __align__(16) __half g_Yt[(size_t)NB * NH * NW * NC3];
__device__ float g_W1f[64 * 64];
__device__ float g_W2f[64 * 64];
__device__ float g_b1f[64];
__device__ float g_b2f[64];
__device__ float g_alpha[192];
__device__ float g_betap[192];
__device__ float g_zero64[64];                 // zero-initialized
__device__ int   g_use_tc;                     // 1 iff tcgen05 path active

// Pre-swizzled fp16 conv weights for tcgen05 SS descriptor:
// slab id = (kh*3 + icb)*2 + nh ; slab = 96 oc rows x 192 K elems (=384B rows)
#define WSLAB_BYTES 36864
#define WSLAB_U32   9216
__device__ __align__(16) uint32_t g_Wp[18 * WSLAB_U32];    // ~663 KB

// fp16 conv weights for mma.sync fallback: [ocb(3)][chunk(12)][kk(9)][ic2(8)][oc pad 72]
#define ICC 16
#define SW_PAD 72
#define CONV_SW2 (9 * 8 * SW_PAD)              // 5184 u32 per (ocb,chunk) slab
__device__ __align__(16) uint32_t g_Wh[3 * 12 * CONV_SW2]; // ~747 KB

// ---------------- PTX helpers ----------------
__device__ __forceinline__ uint32_t elect_one_pred() {
    uint32_t pred;
    asm volatile("{\n\t.reg .pred p;\n\telect.sync _|p, 0xFFFFFFFF;\n\t"
                 "selp.b32 %0, 1, 0, p;\n\t}" : "=r"(pred));
    return pred;
}
__device__ __forceinline__ uint32_t smem_to_u32(const void* p) {
    uint32_t a;
    asm("{ .reg .u64 t; cvta.to.shared.u64 t, %1; cvt.u32.u64 %0, t; }" : "=r"(a) : "l"(p));
    return a;
}
#define MBARRIER_INIT(mb, c) \
    asm volatile("mbarrier.init.shared.b64 [%0], %1;" :: "r"((uint32_t)(mb)), "r"((uint32_t)(c)) : "memory")
#define FENCE_PROXY_ASYNC() \
    asm volatile("fence.proxy.async.shared::cta;" ::: "memory")
#define MBARRIER_WAIT_PARITY(mb, par) do {                                          \
    uint32_t _mb = (uint32_t)(mb), _p = (uint32_t)(par), _d;                        \
    asm volatile("{\n\t.reg .pred p;\n\t"                                           \
        "mbarrier.try_wait.parity.acquire.cta.shared::cta.b64 p, [%1], %2;\n\t"     \
        "selp.b32 %0, 1, 0, p;\n\t}" : "=r"(_d) : "r"(_mb), "r"(_p) : "memory");    \
    if (!_d) {                                                                      \
        asm volatile("{\n\t.reg .pred P1;\n\tWL_%=:\n\t"                            \
            "mbarrier.try_wait.parity.acquire.cta.shared::cta.b64 P1, [%0], %1, 0x989680;\n\t" \
            "@P1 bra.uni WD_%=;\n\tbra.uni WL_%=;\n\tWD_%=:\n\t}"                   \
            :: "r"(_mb), "r"(_p) : "memory");                                       \
    }                                                                               \
} while (0)

#if HAS_TCGEN05
#define TCGEN05_ALLOC(sm, n) \
    asm volatile("tcgen05.alloc.cta_group::1.sync.aligned.shared::cta.b32 [%0], %1;" \
                 :: "r"((uint32_t)(sm)), "r"((uint32_t)(n)) : "memory")
#define TCGEN05_RELINQ() \
    asm volatile("tcgen05.relinquish_alloc_permit.cta_group::1.sync.aligned;")
#define TCGEN05_DEALLOC(t, n) \
    asm volatile("tcgen05.dealloc.cta_group::1.sync.aligned.b32 %0, %1;" :: "r"(t), "r"(n))
#define TCGEN05_COMMIT(mb) \
    asm volatile("tcgen05.commit.cta_group::1.mbarrier::arrive::one.shared::cluster.b64 [%0];" \
                 :: "r"((uint32_t)(mb)) : "memory")
#define TCGEN05_FENCE_AFTER() \
    asm volatile("tcgen05.fence::after_thread_sync;" ::: "memory")
#define TCGEN05_WAIT_LD() \
    asm volatile("tcgen05.wait::ld.sync.aligned;" ::: "memory")
#define TCGEN05_LD_X32(r, ta)                                                       \
    asm volatile("tcgen05.ld.sync.aligned.32x32b.x32.b32 "                          \
        "{%0, %1, %2, %3, %4, %5, %6, %7, %8, %9, %10, %11, %12, %13, %14, %15, "   \
        " %16, %17, %18, %19, %20, %21, %22, %23, %24, %25, %26, %27, %28, %29, %30, %31}, [%32];" \
        : "=r"((r)[0]),  "=r"((r)[1]),  "=r"((r)[2]),  "=r"((r)[3]),                \
          "=r"((r)[4]),  "=r"((r)[5]),  "=r"((r)[6]),  "=r"((r)[7]),                \
          "=r"((r)[8]),  "=r"((r)[9]),  "=r"((r)[10]), "=r"((r)[11]),               \
          "=r"((r)[12]), "=r"((r)[13]), "=r"((r)[14]), "=r"((r)[15]),               \
          "=r"((r)[16]), "=r"((r)[17]), "=r"((r)[18]), "=r"((r)[19]),               \
          "=r"((r)[20]), "=r"((r)[21]), "=r"((r)[22]), "=r"((r)[23]),               \
          "=r"((r)[24]), "=r"((r)[25]), "=r"((r)[26]), "=r"((r)[27]),               \
          "=r"((r)[28]), "=r"((r)[29]), "=r"((r)[30]), "=r"((r)[31])                \
        : "r"(ta))

__device__ __forceinline__ void mma_f16_ss(uint32_t d, uint64_t a, uint64_t b,
                                           uint32_t idesc, uint32_t en)
{
    asm volatile("{\n\t.reg .pred p;\n\tsetp.ne.u32 p, %5, 0;\n\t"
                 "tcgen05.mma.cta_group::1.kind::f16 [%0], %1, %2, %3, {%4,%4,%4,%4}, p;\n\t}"
                 :: "r"(d), "l"(a), "l"(b), "r"(idesc), "r"(0u), "r"(en) : "memory");
}
#endif // HAS_TCGEN05

// SW128 smem descriptor: LBO=1 (16B), SBO=192 (3072B between 8-row groups)
__device__ __forceinline__ uint64_t make_desc_sw128(uint32_t addr) {
    uint64_t d = 0;
    d |= (uint64_t)((addr >> 4) & 0x3FFF);
    d |= (uint64_t)1   << 16;   // LBO = 1
    d |= (uint64_t)192 << 32;   // SBO = 192
    d |= (uint64_t)1   << 46;   // version = 1 (Blackwell)
    d |= (uint64_t)2   << 61;   // layout = SW128
    return d;
}
__device__ __forceinline__ uint32_t sw128(uint32_t off) { return off ^ ((off >> 3) & 0x70); }

// =================================================================
// Kernel 0: fuse weights, BN params, pack both conv weight images
// =================================================================
__global__ void prep_kernel(const float* __restrict__ Wx,  const float* __restrict__ bx,
                            const float* __restrict__ Wx1, const float* __restrict__ bx1,
                            const float* __restrict__ Wx2, const float* __restrict__ bx2,
                            const float* __restrict__ Wg,  const float* __restrict__ b_msa,
                            const float* __restrict__ gamma, const float* __restrict__ beta,
                            const float* __restrict__ mean,  const float* __restrict__ var)
{
    int tid = blockIdx.x * blockDim.x + threadIdx.x;
    int nthr = gridDim.x * blockDim.x;

    if (tid == 0) {
#if HAS_TCGEN05
        g_use_tc = 1;
#else
        g_use_tc = 0;
#endif
    }

    for (int idx = tid; idx < 4096; idx += nthr) {
        int o = idx >> 6, c = idx & 63;
        float s1 = 0.f, s2 = 0.f;
        for (int k = 0; k < 64; k++) {
            float wc = Wx[k * 64 + c];
            s1 = fmaf(Wx1[o * 64 + k], wc, s1);
            s2 = fmaf(Wx2[o * 64 + k], wc, s2);
        }
        g_W1f[idx] = s1;
        g_W2f[idx] = s2;
    }
    for (int o = tid; o < 64; o += nthr) {
        float s1 = bx1[o], s2 = bx2[o];
        for (int k = 0; k < 64; k++) {
            float bk = bx[k];
            s1 = fmaf(Wx1[o * 64 + k], bk, s1);
            s2 = fmaf(Wx2[o * 64 + k], bk, s2);
        }
        g_b1f[o] = s1;
        g_b2f[o] = s2;
    }
    for (int o = tid; o < 192; o += nthr) {
        float a = gamma[o] * rsqrtf(var[o] + 1e-4f);
        g_alpha[o] = a;
        g_betap[o] = fmaf(b_msa[o] - mean[o], a, beta[o]);
    }
    // tcgen05 pack: slab [(kh*3+icb)*2+nh]: 96 oc rows x 192 K (kw*64+ic), SW128
    for (int idx = tid; idx < 18 * WSLAB_U32; idx += nthr) {
        int slab = idx / WSLAB_U32;
        int rem  = idx % WSLAB_U32;
        int nh  = slab & 1;
        int icb = (slab >> 1) % 3;
        int kh  = slab / 6;
        int r32 = rem / 96;          // oc row 0..95
        int c32 = rem % 96;          // u32 col (2 K-elems)
        int kw = c32 / 32;
        int ic = (c32 % 32) * 2;
        int oc_g = nh * 96 + r32;
        const float* wp = Wg + ((size_t)(oc_g * NC3 + icb * 64 + ic) * 3 + kh) * 3 + kw;
        __half2 hv = __floats2half2_rn(wp[0], wp[9]);   // ic, ic+1 (ic stride = 9 floats)
        uint32_t off = ((uint32_t)(r32 >> 3) * 3 + kw) * 1024 + (r32 & 7) * 128 + ic * 2;
        *(uint32_t*)((char*)g_Wp + (size_t)slab * WSLAB_BYTES + sw128(off)) = *(uint32_t*)&hv;
    }
    // mma.sync fallback pack: half2 (ic even, ic odd) transposed to [..][oc]
    for (int idx = tid; idx < 3 * 12 * CONV_SW2; idx += nthr) {
        int ocb_i = idx / (12 * CONV_SW2);
        int rem = idx % (12 * CONV_SW2);
        int chunk = rem / CONV_SW2;
        int s = rem % CONV_SW2;
        int kk = s / (8 * SW_PAD);
        int s2 = s % (8 * SW_PAD);
        int ic2 = s2 / SW_PAD;
        int oc = s2 % SW_PAD;
        uint32_t v = 0;
        if (oc < 64) {
            const float* wp = Wg + (size_t)(ocb_i * 64 + oc) * (NC3 * 9)
                              + (chunk * ICC + 2 * ic2) * 9 + kk;
            __half2 hv = __floats2half2_rn(wp[0], wp[9]);
            v = *(uint32_t*)&hv;
        }
        g_Wh[idx] = v;
    }
}

// =================================================================
// Kernel 1: per-(b,h) attention stage (emits transposed fp16 g_Yt)
// =================================================================
#define LDM 132
#define LDT 68

#define OFF_A  0
#define OFF_P  (64 * LDM)
#define OFF_B1 (2 * 64 * LDM)
#define OFF_B2 (3 * 64 * LDM)
#define OFF_FT (4 * 64 * LDM)
#define OFF_ST (OFF_FT + 128 * LDT)
#define OFF_WT (OFF_ST + 64 * LDT)
#define ATTN_SMEM_FLOATS (OFF_WT + 64 * LDT)   // 51200 floats = 204800 B

__device__ __forceinline__ void load_wt(float* sWt, const float* __restrict__ G, int tid)
{
    for (int idx = tid; idx < 4096; idx += 256) {
        int o = idx >> 6, k = idx & 63;
        sWt[k * LDT + o] = G[idx];
    }
}

__device__ __forceinline__ void load_tile(float* sA, const float* __restrict__ X,
                                          int b, int h, int tid)
{
    const float* src = X + (size_t)b * 64 * HW + h * NW;
    for (int idx = tid; idx < 8192; idx += 256) {
        int c = idx >> 7, w = idx & 127;
        sA[c * LDM + w] = src[c * HW + w];
    }
}

// C[o][w] (stride LDM, 64x128) in smem -> transposed fp16 store to g_Yt row base
__device__ __forceinline__ void store_t_fp16(const float* __restrict__ sC,
                                             __half* __restrict__ dst, int tid)
{
    for (int idx = tid; idx < 1024; idx += 256) {
        int q = idx & 7, w = idx >> 3;
        const float* src = sC + (q * 8) * LDM + w;
        __half2 p0 = __floats2half2_rn(src[0],       src[LDM]);
        __half2 p1 = __floats2half2_rn(src[2 * LDM], src[3 * LDM]);
        __half2 p2 = __floats2half2_rn(src[4 * LDM], src[5 * LDM]);
        __half2 p3 = __floats2half2_rn(src[6 * LDM], src[7 * LDM]);
        uint4 v;
        v.x = *(uint32_t*)&p0; v.y = *(uint32_t*)&p1;
        v.z = *(uint32_t*)&p2; v.w = *(uint32_t*)&p3;
        *(uint4*)(dst + (size_t)w * NC3 + q * 8) = v;
    }
}

__device__ __forceinline__ void gemm_ow(const float* __restrict__ sWt,
                                        const float* __restrict__ sA,
                                        float* __restrict__ outp,
                                        const float* __restrict__ bias, int tid)
{
    int oc0 = (tid >> 4) << 2;
    int w0  = (tid & 15) << 3;
    float acc[4][8];
#pragma unroll
    for (int i = 0; i < 4; i++) {
        float bb = bias[oc0 + i];
#pragma unroll
        for (int j = 0; j < 8; j++) acc[i][j] = bb;
    }
#pragma unroll 4
    for (int k = 0; k < 64; k++) {
        float4 a0 = *(const float4*)(sA + k * LDM + w0);
        float4 a1 = *(const float4*)(sA + k * LDM + w0 + 4);
        float av[8] = {a0.x, a0.y, a0.z, a0.w, a1.x, a1.y, a1.z, a1.w};
#pragma unroll
        for (int i = 0; i < 4; i++) {
            float wv = sWt[k * LDT + oc0 + i];
#pragma unroll
            for (int j = 0; j < 8; j++) acc[i][j] = fmaf(wv, av[j], acc[i][j]);
        }
    }
#pragma unroll
    for (int i = 0; i < 4; i++) {
        *(float4*)(outp + (oc0 + i) * LDM + w0)     = make_float4(acc[i][0], acc[i][1], acc[i][2], acc[i][3]);
        *(float4*)(outp + (oc0 + i) * LDM + w0 + 4) = make_float4(acc[i][4], acc[i][5], acc[i][6], acc[i][7]);
    }
}

__device__ __forceinline__ void gemm_tr(const float* __restrict__ sWt,
                                        const float* __restrict__ sA,
                                        float* __restrict__ sFT,
                                        const float* __restrict__ bias, int tid)
{
    int w0 = (tid >> 4) << 3;
    int d0 = (tid & 15) << 2;
    float acc[8][4];
#pragma unroll
    for (int j = 0; j < 4; j++) {
        float bb = bias[d0 + j];
#pragma unroll
        for (int i = 0; i < 8; i++) acc[i][j] = bb;
    }
#pragma unroll 4
    for (int k = 0; k < 64; k++) {
        float4 a0 = *(const float4*)(sA + k * LDM + w0);
        float4 a1 = *(const float4*)(sA + k * LDM + w0 + 4);
        float av[8] = {a0.x, a0.y, a0.z, a0.w, a1.x, a1.y, a1.z, a1.w};
#pragma unroll
        for (int j = 0; j < 4; j++) {
            float wv = sWt[k * LDT + d0 + j];
#pragma unroll
            for (int i = 0; i < 8; i++) acc[i][j] = fmaf(av[i], wv, acc[i][j]);
        }
    }
#pragma unroll
    for (int i = 0; i < 8; i++)
        *(float4*)(sFT + (w0 + i) * LDT + d0) = make_float4(acc[i][0], acc[i][1], acc[i][2], acc[i][3]);
}

__device__ __forceinline__ void gemm_score(const float* __restrict__ sB,
                                           const float* __restrict__ sFT,
                                           float* __restrict__ sSt, int tid)
{
    int c0 = (tid >> 4) << 2;
    int d0 = (tid & 15) << 2;
    float acc[4][4];
#pragma unroll
    for (int i = 0; i < 4; i++)
#pragma unroll
        for (int j = 0; j < 4; j++) acc[i][j] = 0.f;
#pragma unroll 4
    for (int k = 0; k < 128; k++) {
        float4 f = *(const float4*)(sFT + k * LDT + d0);
        float fv[4] = {f.x, f.y, f.z, f.w};
#pragma unroll
        for (int i = 0; i < 4; i++) {
            float bv = sB[(c0 + i) * LDM + k];
#pragma unroll
            for (int j = 0; j < 4; j++) acc[i][j] = fmaf(bv, fv[j], acc[i][j]);
        }
    }
#pragma unroll
    for (int i = 0; i < 4; i++)
#pragma unroll
        for (int j = 0; j < 4; j++)
            sSt[(d0 + j) * LDT + c0 + i] = acc[i][j];
}

__global__ void __launch_bounds__(256) attn_kernel(
    const float* __restrict__ x,  const float* __restrict__ xf, const float* __restrict__ xr,
    const float* __restrict__ Wx, const float* __restrict__ bx,
    const float* __restrict__ Wxf, const float* __restrict__ bxf,
    const float* __restrict__ Wxr, const float* __restrict__ bxr)
{
    extern __shared__ float smem[];
    float* sA  = smem + OFF_A;
    float* sP  = smem + OFF_P;
    float* sB1 = smem + OFF_B1;
    float* sB2 = smem + OFF_B2;
    float* sFT = smem + OFF_FT;
    float* sSt = smem + OFF_ST;
    float* sWt = smem + OFF_WT;

    int tid = threadIdx.x;
    int bh = blockIdx.x;
    int b = bh >> 7, h = bh & 127;
    __half* yrow = g_Yt + ((size_t)(b * NH + h) * NW) * NC3;

    load_tile(sA, x, b, h, tid);
    load_wt(sWt, Wx, tid);
    __syncthreads();

    store_t_fp16(sA, yrow + 128, tid);             // x_org -> ch [128,192)
    gemm_ow(sWt, sA, sP, bx, tid);                 // xp
    __syncthreads();
    load_wt(sWt, g_W1f, tid);
    __syncthreads();
    gemm_ow(sWt, sA, sB1, g_b1f, tid);             // x1
    __syncthreads();
    load_wt(sWt, g_W2f, tid);
    __syncthreads();
    gemm_ow(sWt, sA, sB2, g_b2f, tid);             // x2
    __syncthreads();

    // ---- xf path ----
    load_tile(sA, xf, b, h, tid);
    load_wt(sWt, Wxf, tid);
    __syncthreads();
    gemm_tr(sWt, sA, sFT, bxf, tid);               // xfp^T
    __syncthreads();
    gemm_score(sB1, sFT, sSt, tid);                // score1^T
    __syncthreads();
    gemm_ow(sSt, sP, sFT, g_zero64, tid);          // feature_xf -> sFT staging
    __syncthreads();
    store_t_fp16(sFT, yrow + 0, tid);              // -> ch [0,64)

    // ---- xr path ----
    load_tile(sA, xr, b, h, tid);
    load_wt(sWt, Wxr, tid);
    __syncthreads();
    gemm_tr(sWt, sA, sFT, bxr, tid);               // xrp^T
    __syncthreads();
    gemm_score(sB2, sFT, sSt, tid);                // score2^T
    __syncthreads();
    gemm_ow(sSt, sP, sFT, g_zero64, tid);          // feature_xr
    __syncthreads();
    store_t_fp16(sFT, yrow + 64, tid);             // -> ch [64,128)
}

// =================================================================
// Kernel 2a: conv via tcgen05 (SS, kind::f16)  [compiled only on *a target]
// =================================================================
#define ISLAB_BYTES 49152
#define SM_IN    1024
#define SM_W0    (SM_IN + 2 * ISLAB_BYTES)
#define SM_W1    (SM_W0 + WSLAB_BYTES)
#define CONV_SMEM_BYTES (SM_W1 + WSLAB_BYTES)  // 173056

// idesc: dtype=F32(1<<4), atype=btype=F16(0), N=96 -> 12<<17, M=128 -> 8<<24
#define CONV_IDESC ((1u << 4) | (12u << 17) | (8u << 24))

__global__ void __launch_bounds__(256) conv_tc_kernel(float* __restrict__ out)
{
#if HAS_TCGEN05
    extern __shared__ char csm[];
    uint32_t smem_base = smem_to_u32(csm);
    uint32_t mbar = smem_base + 8;

    int tid = threadIdx.x;
    int wid = tid >> 5, lane = tid & 31;
    int h2 = blockIdx.x;       // 0..63
    int b  = blockIdx.y;       // 0..7

    if (wid == 0) TCGEN05_ALLOC(smem_base + 0, 512);
    else if (wid == 1) TCGEN05_RELINQ();
    if (tid == 0) MBARRIER_INIT(mbar, 1);
    __syncthreads();
    uint32_t tmem_base;
    asm volatile("ld.shared.b32 %0, [%1];" : "=r"(tmem_base) : "r"(smem_base + 0));

    uint64_t descA  = make_desc_sw128(smem_base + SM_IN);
    uint64_t descB0 = make_desc_sw128(smem_base + SM_W0);
    uint64_t descB1 = make_desc_sw128(smem_base + SM_W1);

    const __half* Ybase = g_Yt + (size_t)b * NH * NW * NC3;

    for (int t = 0; t < 9; t++) {
        int kh = t / 3, icb = t % 3;
        if (t > 0) MBARRIER_WAIT_PARITY(mbar, (t - 1) & 1);

        // stage input: 2 planes (s) x 128 w x [kw*64+ic] K-rows, SW128 image
        for (int idx = tid; idx < 2 * 128 * 3 * 8; idx += 256) {
            int q  = idx & 7;
            int r1 = idx >> 3;
            int kw = r1 % 3;
            int r2 = r1 / 3;
            int w  = r2 & 127;
            int s  = r2 >> 7;
            int h_in = 2 * h2 + kh + s - 1;
            int w_in = w + kw - 1;
            uint4 v = make_uint4(0u, 0u, 0u, 0u);
            if ((unsigned)h_in < 128u && (unsigned)w_in < 128u)
                v = *(const uint4*)(Ybase + ((size_t)h_in * NW + w_in) * NC3 + icb * 64 + q * 8);
            uint32_t off = ((uint32_t)(w >> 3) * 3 + kw) * 1024 + (w & 7) * 128 + q * 16;
            *(uint4*)(csm + SM_IN + s * ISLAB_BYTES + sw128(off)) = v;
        }
        // stage weights (verbatim, pre-swizzled): 2 nh slabs
        {
            const uint4* src = (const uint4*)(g_Wp + (size_t)(t * 2) * WSLAB_U32);
            uint4* dst = (uint4*)(csm + SM_W0);
            for (int idx = tid; idx < 2 * WSLAB_U32 / 4; idx += 256)
                dst[idx] = src[idx];
        }
        FENCE_PROXY_ASYNC();
        __syncthreads();

        if (wid == 0 && elect_one_pred()) {
#pragma unroll
            for (int nh = 0; nh < 2; nh++) {
                uint64_t bdesc = nh ? descB1 : descB0;
#pragma unroll
                for (int r = 0; r < 2; r++) {
#pragma unroll
                    for (int ks = 0; ks < 12; ks++) {
                        uint64_t koff = (uint64_t)((ks >> 2) * 64 + (ks & 3) * 2);
                        mma_f16_ss(tmem_base + r * 192 + nh * 96,
                                   descA + (uint64_t)(r * 3072) + koff,
                                   bdesc + koff,
                                   CONV_IDESC,
                                   (t == 0 && ks == 0) ? 0u : 1u);
                    }
                }
            }
            TCGEN05_COMMIT(mbar);
        }
        __syncthreads();
    }

    MBARRIER_WAIT_PARITY(mbar, 0);     // 9th commit: phase 8, parity 0
    TCGEN05_FENCE_AFTER();

    int r = wid >> 2;
    int w = (wid & 3) * 32 + lane;
    int h = 2 * h2 + r;
#pragma unroll
    for (int c = 0; c < 6; c++) {
        uint32_t regs[32];
        TCGEN05_LD_X32(regs, tmem_base + r * 192 + c * 32);
        TCGEN05_WAIT_LD();
#pragma unroll
        for (int i = 0; i < 32; i++) {
            int oc = c * 32 + i;
            float v = __uint_as_float(regs[i]);
            v = fmaxf(fmaf(v, g_alpha[oc], g_betap[oc]), 0.f);
            out[((size_t)(b * NC3 + oc) * NH + h) * NW + w] = v;
        }
    }
    __syncthreads();
    if (wid == 0) TCGEN05_DEALLOC(tmem_base, 512);
#endif // HAS_TCGEN05
}

// =================================================================
// Kernel 2b: conv via mma.sync fp16 (fallback, reads g_Yt)
// =================================================================
#define LDI 136
#define CONV_SIN2 (8 * 3 * LDI)
#define CONV_FB_SMEM_U32 (CONV_SIN2 + CONV_SW2)   // 8448 u32 = 33792 B

__device__ __forceinline__ void mma_f16_sync(float4& c, const uint32_t* a, const uint32_t* b)
{
    asm volatile("mma.sync.aligned.m16n8k16.row.col.f32.f16.f16.f32 "
                 "{%0,%1,%2,%3}, {%4,%5,%6,%7}, {%8,%9}, {%0,%1,%2,%3};"
                 : "+f"(c.x), "+f"(c.y), "+f"(c.z), "+f"(c.w)
                 : "r"(a[0]), "r"(a[1]), "r"(a[2]), "r"(a[3]), "r"(b[0]), "r"(b[1]));
}

__global__ void __launch_bounds__(256, 3) conv_mma_kernel(float* __restrict__ out)
{
    if (g_use_tc) return;              // tcgen05 path handled the conv

    extern __shared__ uint32_t csmem[];
    uint32_t* sIn = csmem;
    uint32_t* sW  = csmem + CONV_SIN2;

    int tid = threadIdx.x;
    int lane = tid & 31, warp = tid >> 5;
    int ocb = blockIdx.x;
    int h = blockIdx.y;
    int b = blockIdx.z;
    int warp_oc = (warp >> 2) * 32;
    int warp_w  = (warp & 3) * 32;
    int g = lane >> 2, r = lane & 3;

    float4 Cacc[2][4];
#pragma unroll
    for (int mi = 0; mi < 2; mi++)
#pragma unroll
        for (int nj = 0; nj < 4; nj++) Cacc[mi][nj] = make_float4(0.f, 0.f, 0.f, 0.f);

    const __half* Yb = g_Yt + (size_t)b * NH * NW * NC3;
    const uint32_t* WhB = g_Wh + (size_t)ocb * 12 * CONV_SW2;

    for (int chunk = 0; chunk < 12; chunk++) {
        for (int idx = tid; idx < 8 * 3 * 132; idx += 256) {
            int wc = idx % 132;
            int t = idx / 132;
            int rr = t % 3, ic2 = t / 3;
            int h_in = h + rr - 1;
            int w_in = wc - 1;
            uint32_t v = 0;
            if ((unsigned)h_in < 128u && (unsigned)w_in < 128u)
                v = *(const uint32_t*)(Yb + ((size_t)h_in * NW + w_in) * NC3
                                       + chunk * ICC + ic2 * 2);
            sIn[ic2 * (3 * LDI) + rr * LDI + wc] = v;
        }
        {
            const uint4* src = (const uint4*)(WhB + (size_t)chunk * CONV_SW2);
            uint4* dst = (uint4*)sW;
            for (int idx = tid; idx < CONV_SW2 / 4; idx += 256)
                dst[idx] = src[idx];
        }
        __syncthreads();

#pragma unroll
        for (int kk = 0; kk < 9; kk++) {
            int kh = kk / 3, kw = kk % 3;
            const uint32_t* wb = sW + kk * (8 * SW_PAD) + warp_oc + g;
            const uint32_t* ib = sIn + kh * LDI + warp_w + g + kw;
            uint32_t afr[2][4];
            uint32_t bfr[4][2];
#pragma unroll
            for (int mi = 0; mi < 2; mi++) {
                const uint32_t* wa = wb + mi * 16;
                afr[mi][0] = wa[r * SW_PAD];
                afr[mi][1] = wa[r * SW_PAD + 8];
                afr[mi][2] = wa[(r + 4) * SW_PAD];
                afr[mi][3] = wa[(r + 4) * SW_PAD + 8];
            }
#pragma unroll
            for (int nj = 0; nj < 4; nj++) {
                bfr[nj][0] = ib[r * (3 * LDI) + nj * 8];
                bfr[nj][1] = ib[(r + 4) * (3 * LDI) + nj * 8];
            }
#pragma unroll
            for (int mi = 0; mi < 2; mi++)
#pragma unroll
                for (int nj = 0; nj < 4; nj++)
                    mma_f16_sync(Cacc[mi][nj], afr[mi], bfr[nj]);
        }
        __syncthreads();
    }

#pragma unroll
    for (int mi = 0; mi < 2; mi++) {
        int oc_lo = ocb * 64 + warp_oc + mi * 16 + g;
        int oc_hi = oc_lo + 8;
        float al0 = g_alpha[oc_lo], bp0 = g_betap[oc_lo];
        float al1 = g_alpha[oc_hi], bp1 = g_betap[oc_hi];
        float* row0 = out + ((size_t)b * NC3 + oc_lo) * HW + h * NW;
        float* row1 = out + ((size_t)b * NC3 + oc_hi) * HW + h * NW;
#pragma unroll
        for (int nj = 0; nj < 4; nj++) {
            int w = warp_w + nj * 8 + 2 * r;
            float2 v0, v1;
            v0.x = fmaxf(fmaf(Cacc[mi][nj].x, al0, bp0), 0.f);
            v0.y = fmaxf(fmaf(Cacc[mi][nj].y, al0, bp0), 0.f);
            v1.x = fmaxf(fmaf(Cacc[mi][nj].z, al1, bp1), 0.f);
            v1.y = fmaxf(fmaf(Cacc[mi][nj].w, al1, bp1), 0.f);
            *(float2*)(row0 + w) = v0;
            *(float2*)(row1 + w) = v1;
        }
    }
}

// =================================================================
// launch
// =================================================================
extern "C" void kernel_launch(void* const* d_in, const int* in_sizes, int n_in,
                              void* d_out, int out_size)
{
    const float* x     = (const float*)d_in[0];
    const float* xf    = (const float*)d_in[1];
    const float* xr    = (const float*)d_in[2];
    const float* Wx    = (const float*)d_in[3];
    const float* bx    = (const float*)d_in[4];
    const float* Wx1   = (const float*)d_in[5];
    const float* bx1   = (const float*)d_in[6];
    const float* Wx2   = (const float*)d_in[7];
    const float* bx2   = (const float*)d_in[8];
    const float* Wxf   = (const float*)d_in[9];
    const float* bxf   = (const float*)d_in[10];
    const float* Wxr   = (const float*)d_in[11];
    const float* bxr   = (const float*)d_in[12];
    const float* W_msa = (const float*)d_in[13];
    const float* b_msa = (const float*)d_in[14];
    const float* gamma = (const float*)d_in[15];
    const float* beta  = (const float*)d_in[16];
    const float* mean  = (const float*)d_in[17];
    const float* var   = (const float*)d_in[18];
    float* out = (float*)d_out;

    cudaFuncSetAttribute(attn_kernel, cudaFuncAttributeMaxDynamicSharedMemorySize,
                         ATTN_SMEM_FLOATS * sizeof(float));
    cudaFuncSetAttribute(conv_tc_kernel, cudaFuncAttributeMaxDynamicSharedMemorySize,
                         CONV_SMEM_BYTES);
    cudaFuncSetAttribute(conv_mma_kernel, cudaFuncAttributeMaxDynamicSharedMemorySize,
                         CONV_FB_SMEM_U32 * sizeof(uint32_t));

    prep_kernel<<<128, 256>>>(Wx, bx, Wx1, bx1, Wx2, bx2, W_msa, b_msa,
                              gamma, beta, mean, var);

    attn_kernel<<<NB * NH, 256, ATTN_SMEM_FLOATS * sizeof(float)>>>(
        x, xf, xr, Wx, bx, Wxf, bxf, Wxr, bxr);

    conv_tc_kernel<<<dim3(NH / 2, NB), 256, CONV_SMEM_BYTES>>>(out);
    conv_mma_kernel<<<dim3(3, NH, NB), 256, CONV_FB_SMEM_U32 * sizeof(uint32_t)>>>(out);
}